// round 1
// baseline (speedup 1.0000x reference)
#include <cuda_runtime.h>
#include <cuda_bf16.h>
#include <cstdint>

// Problem shape (fixed by dataset)
#define BB 64
#define LL 256
#define TT 1600
#define NEGV (-1e30f)

// Scratch for per-batch alpha_last (allocation-free rule: __device__ global)
__device__ float g_alpha_last[BB];

// ---------------------------------------------------------------------------
// Kernel 1: elementwise log(probs + 1e-30) -> output matrix region.
// probs is 16B-aligned; out matrix lives at out+1 (4B-aligned), so we do
// float4 loads + 4 scalar stores (scalar stores still coalesce warp-wide).
// ---------------------------------------------------------------------------
__global__ void k_elementwise_log(const float* __restrict__ probs,
                                  float* __restrict__ mat,  // = out + 1
                                  long long nvec)           // number of float4
{
    long long i = (long long)blockIdx.x * blockDim.x + threadIdx.x;
    long long stride = (long long)gridDim.x * blockDim.x;
    const float4* p4 = reinterpret_cast<const float4*>(probs);
    for (; i < nvec; i += stride) {
        float4 v = p4[i];
        long long o = i * 4;
        mat[o + 0] = __logf(v.x + 1e-30f);
        mat[o + 1] = __logf(v.y + 1e-30f);
        mat[o + 2] = __logf(v.z + 1e-30f);
        mat[o + 3] = __logf(v.w + 1e-30f);
    }
}

// ---------------------------------------------------------------------------
// Kernel 2: forward recursion. One warp per batch (64 blocks x 32 threads).
// Lane i owns labels [8i, 8i+8). State in registers; intra-warp shift via
// shfl_up; lp streamed from the precomputed log matrix with 2-deep prefetch.
// ---------------------------------------------------------------------------
__device__ __forceinline__ float lae(float x, float y)
{
    float m = fmaxf(x, y);
    float d = fminf(x, y) - m;        // <= 0; 0 if equal (incl. both NEG)
    d = fmaxf(d, -88.0f);             // keep __expf well-defined
    return m + __logf(1.0f + __expf(d));
}

__global__ void __launch_bounds__(32, 1)
k_recursion(const float* __restrict__ mat,       // [B, L, T] log probs
            const int* __restrict__ text_lengths,
            const int* __restrict__ mel_lengths)
{
    const int b    = blockIdx.x;
    const int lane = threadIdx.x;

    const int tgt_t = mel_lengths[b] - 1;   // final time index
    const int tgt_l = text_lengths[b] - 1;  // final label index

    // Base pointer for this lane's first label row
    const float* rowbase = mat + (size_t)b * LL * TT + (size_t)(lane * 8) * TT;

    // alpha state: 8 labels per lane
    float a[8];
#pragma unroll
    for (int j = 0; j < 8; ++j) a[j] = NEGV;
    if (lane == 0) a[0] = rowbase[0];       // log_alpha[0][0] = lp[0][0]

    // 2-deep prefetch buffers for lp at t+0 (consumed), t+1, t+2
    float nb0[8], nb1[8];
    {
        int tA = (tgt_t < 1) ? tgt_t : 1;
        int tB = (tgt_t < 2) ? tgt_t : 2;
#pragma unroll
        for (int j = 0; j < 8; ++j) nb0[j] = __ldg(rowbase + j * TT + tA);
#pragma unroll
        for (int j = 0; j < 8; ++j) nb1[j] = __ldg(rowbase + j * TT + tB);
    }

    for (int t = 1; t <= tgt_t; ++t) {
        float lp[8];
#pragma unroll
        for (int j = 0; j < 8; ++j) { lp[j] = nb0[j]; nb0[j] = nb1[j]; }
        int tp = t + 2; if (tp > tgt_t) tp = tgt_t;
#pragma unroll
        for (int j = 0; j < 8; ++j) nb1[j] = __ldg(rowbase + j * TT + tp);

        // shifted value entering this lane's label 8*lane comes from the
        // previous lane's label 8*lane-1 (its a[7]) of the OLD state.
        float top = __shfl_up_sync(0xffffffffu, a[7], 1);
        if (lane == 0) top = NEGV;

        float na[8];
        na[0] = lae(a[0], top) + lp[0];
#pragma unroll
        for (int j = 1; j < 8; ++j)
            na[j] = lae(a[j], a[j - 1]) + lp[j];
#pragma unroll
        for (int j = 0; j < 8; ++j) a[j] = na[j];
    }

    // Extract alpha at (tgt_t, tgt_l)
    if (lane == (tgt_l >> 3)) {
        int sub = tgt_l & 7;
        float v = a[0];
#pragma unroll
        for (int j = 1; j < 8; ++j) if (sub == j) v = a[j];
        g_alpha_last[b] = v;
    }
}

// ---------------------------------------------------------------------------
// Kernel 3: reduce 64 partials -> loss = -mean
// ---------------------------------------------------------------------------
__global__ void k_reduce(float* __restrict__ loss_out)
{
    int i = threadIdx.x; // 32 threads
    float v = g_alpha_last[i] + g_alpha_last[i + 32];
#pragma unroll
    for (int off = 16; off > 0; off >>= 1)
        v += __shfl_down_sync(0xffffffffu, v, off);
    if (i == 0) loss_out[0] = -v * (1.0f / BB);
}

// ---------------------------------------------------------------------------
extern "C" void kernel_launch(void* const* d_in, const int* in_sizes, int n_in,
                              void* d_out, int out_size)
{
    const float* probs        = (const float*)d_in[0];
    // d_in[1] = melspec (unused by the computation)
    const int*   text_lengths = (const int*)d_in[2];
    const int*   mel_lengths  = (const int*)d_in[3];

    float* out = (float*)d_out;
    // Output tuple flattened in order: (mdn_loss[1], log_prob_matrix[B*L*T])
    float* loss_ptr = out;
    float* mat      = out + 1;

    const long long nelem = (long long)BB * LL * TT;   // 26,214,400
    const long long nvec  = nelem / 4;                  // divisible by 4

    k_elementwise_log<<<1184, 256>>>(probs, mat, nvec);
    k_recursion<<<BB, 32>>>(mat, text_lengths, mel_lengths);
    k_reduce<<<1, 32>>>(loss_ptr);
    (void)in_sizes; (void)n_in; (void)out_size;
}

// round 2
// speedup vs baseline: 1.6481x; 1.6481x over previous
#include <cuda_runtime.h>
#include <cuda_bf16.h>
#include <cstdint>

// Problem shape (fixed by dataset)
#define BB 64
#define LL 256
#define TT 1600
#define NEGV (-1e30f)
#define E_TOTAL (BB * LL * TT)          // 26,214,400
#define NE_BLOCKS 25600                 // elementwise blocks: 25600*256 = E_TOTAL/4

// Scratch for per-batch alpha_last (allocation-free rule: __device__ global)
__device__ float g_alpha_last[BB];

__device__ __forceinline__ float lae(float x, float y)
{
    float m = fmaxf(x, y);
    float d = fminf(x, y) - m;        // <= 0; 0 if equal (incl. both NEG)
    d = fmaxf(d, -88.0f);             // keep __expf well-defined
    return m + __logf(1.0f + __expf(d));
}

// ---------------------------------------------------------------------------
// Fused kernel.
//   blocks [0, BB)            : forward recursion, one batch per block,
//                               128 active threads (4 warps), 2 labels/thread.
//                               Reads RAW probs, applies log inline -> no
//                               dependency on the elementwise pass.
//   blocks [BB, BB+NE_BLOCKS) : elementwise log(probs+1e-30) -> out matrix,
//                               one float4 store per thread, stores 16B-aligned
//                               (window shifted by 1 to absorb the out+1 offset).
// Both roles run concurrently in one launch.
// ---------------------------------------------------------------------------
__global__ void __launch_bounds__(256)
k_fused(const float* __restrict__ probs,
        const int* __restrict__ text_lengths,
        const int* __restrict__ mel_lengths,
        float* __restrict__ out)
{
    if (blockIdx.x >= BB) {
        // ---------------- elementwise role ----------------
        // out[i] = log(probs[i-1] + 1e-30) for i in [1, E_TOTAL].
        // Thread m (m>=1) stores float4 at out+4m  <-  probs[4m-1 .. 4m+2].
        unsigned m = (blockIdx.x - BB) * 256u + threadIdx.x;
        if (m == 0) {
            // stragglers: out[1..3] and out[E_TOTAL]
            out[1] = __logf(__ldg(probs + 0) + 1e-30f);
            out[2] = __logf(__ldg(probs + 1) + 1e-30f);
            out[3] = __logf(__ldg(probs + 2) + 1e-30f);
            out[(size_t)E_TOTAL] = __logf(__ldg(probs + E_TOTAL - 1) + 1e-30f);
        } else {
            float4 v = __ldg(reinterpret_cast<const float4*>(probs) + m);
            float prev = __ldg(probs + 4 * (size_t)m - 1);   // L1 hit (neighbor's .w)
            float4 o;
            o.x = __logf(prev + 1e-30f);
            o.y = __logf(v.x + 1e-30f);
            o.z = __logf(v.y + 1e-30f);
            o.w = __logf(v.z + 1e-30f);
            *reinterpret_cast<float4*>(out + 4 * (size_t)m) = o;
        }
        return;
    }

    // ---------------- recursion role ----------------
    const int b   = blockIdx.x;
    const int tid = threadIdx.x;
    if (tid >= 128) return;           // 4 warps do the work

    const int tgt_t = __ldg(mel_lengths + b)  - 1;   // final time index
    const int tgt_l = __ldg(text_lengths + b) - 1;   // final label index

    const int warp = tid >> 5;
    const int lane = tid & 31;

    // Labels 2*tid and 2*tid+1
    const float* base0 = probs + (size_t)b * LL * TT + (size_t)(2 * tid) * TT;
    const float* base1 = base0 + TT;

    // Double-buffered cross-warp boundary values (lane31.a1 of warps 0..2)
    __shared__ float bnd[2][4];
    if (tid < 4) { bnd[0][tid] = NEGV; bnd[1][tid] = NEGV; }

    float a0 = NEGV, a1 = NEGV;
    if (tid == 0) a0 = __logf(__ldg(base0) + 1e-30f);   // alpha[0][0] = lp[0][0]

    // 4-deep prefetch ring of raw probs for t = 1..
    float pb0[4], pb1[4];
#pragma unroll
    for (int d = 0; d < 4; ++d) {
        int tq = 1 + d; if (tq > tgt_t) tq = tgt_t;
        pb0[d] = __ldg(base0 + tq);
        pb1[d] = __ldg(base1 + tq);
    }
    __syncthreads();

#pragma unroll 4
    for (int t = 1; t <= tgt_t; ++t) {
        const int r = (t - 1) & 3;
        float lp0 = __logf(pb0[r] + 1e-30f);
        float lp1 = __logf(pb1[r] + 1e-30f);
        int tq = t + 4; if (tq > tgt_t) tq = tgt_t;
        pb0[r] = __ldg(base0 + tq);
        pb1[r] = __ldg(base1 + tq);

        // left neighbor of label 2*tid = label 2*tid-1 (prev thread's a1).
        // shfl operand is the PREVIOUS step's a1 -> its latency overlaps lae.
        float sh = __shfl_up_sync(0xffffffffu, a1, 1);
        float left0 = (lane == 0) ? ((warp == 0) ? NEGV : bnd[t & 1][warp - 1])
                                  : sh;

        float n0 = lae(a0, left0) + lp0;
        float n1 = lae(a1, a0)    + lp1;
        a0 = n0; a1 = n1;

        if (lane == 31 && warp < 3) bnd[(t + 1) & 1][warp] = a1;
        __syncthreads();
    }

    if (tid == (tgt_l >> 1))
        g_alpha_last[b] = (tgt_l & 1) ? a1 : a0;
}

// ---------------------------------------------------------------------------
// Reduce 64 partials -> loss = -mean
// ---------------------------------------------------------------------------
__global__ void k_reduce(float* __restrict__ loss_out)
{
    int i = threadIdx.x; // 32 threads
    float v = g_alpha_last[i] + g_alpha_last[i + 32];
#pragma unroll
    for (int off = 16; off > 0; off >>= 1)
        v += __shfl_down_sync(0xffffffffu, v, off);
    if (i == 0) loss_out[0] = -v * (1.0f / BB);
}

// ---------------------------------------------------------------------------
extern "C" void kernel_launch(void* const* d_in, const int* in_sizes, int n_in,
                              void* d_out, int out_size)
{
    const float* probs        = (const float*)d_in[0];
    // d_in[1] = melspec (unused by the computation)
    const int*   text_lengths = (const int*)d_in[2];
    const int*   mel_lengths  = (const int*)d_in[3];

    float* out = (float*)d_out;   // out[0] = loss, out[1..E_TOTAL] = log matrix

    k_fused<<<BB + NE_BLOCKS, 256>>>(probs, text_lengths, mel_lengths, out);
    k_reduce<<<1, 32>>>(out);
    (void)in_sizes; (void)n_in; (void)out_size;
}

// round 3
// speedup vs baseline: 1.6936x; 1.0276x over previous
#include <cuda_runtime.h>
#include <cuda_bf16.h>
#include <cstdint>

// Problem shape (fixed by dataset)
#define BB 64
#define LL 256
#define TT 1600
#define NEGV (-1e30f)
#define E_TOTAL (BB * LL * TT)          // 26,214,400
#define NE_BLOCKS 25600                 // elementwise blocks: 25600*256 = E_TOTAL/4
#define PF 16                           // prefetch depth (power of 2)

// Scratch for per-batch alpha_last (allocation-free rule: __device__ global)
__device__ float g_alpha_last[BB];

// logaddexp(x,y) + lp, with (m+lp) off the exp/log chain.
__device__ __forceinline__ float lae_add(float x, float y, float lp)
{
    float m = fmaxf(x, y);
    float d = fminf(x, y) - m;          // <= 0, finite; EX2 underflows to 0 safely
    float s = m + lp;                   // runs parallel to exp/log chain
    return s + __logf(1.0f + __expf(d));
}

// ---------------------------------------------------------------------------
// Fused kernel.
//   blocks [0, BB)            : forward recursion, one batch per block,
//                               128 active threads (4 warps), 2 labels/thread,
//                               16-deep register prefetch ring of raw probs.
//   blocks [BB, BB+NE_BLOCKS) : elementwise log(probs+1e-30) -> out matrix,
//                               one float4 store per thread, stores 16B-aligned.
// ---------------------------------------------------------------------------
__global__ void __launch_bounds__(256)
k_fused(const float* __restrict__ probs,
        const int* __restrict__ text_lengths,
        const int* __restrict__ mel_lengths,
        float* __restrict__ out)
{
    if (blockIdx.x >= BB) {
        // ---------------- elementwise role ----------------
        // out[i] = log(probs[i-1] + 1e-30) for i in [1, E_TOTAL].
        unsigned m = (blockIdx.x - BB) * 256u + threadIdx.x;
        if (m == 0) {
            out[1] = __logf(__ldg(probs + 0) + 1e-30f);
            out[2] = __logf(__ldg(probs + 1) + 1e-30f);
            out[3] = __logf(__ldg(probs + 2) + 1e-30f);
            out[(size_t)E_TOTAL] = __logf(__ldg(probs + E_TOTAL - 1) + 1e-30f);
        } else {
            float4 v = __ldg(reinterpret_cast<const float4*>(probs) + m);
            float prev = __ldg(probs + 4 * (size_t)m - 1);   // L1 hit (neighbor's .w)
            float4 o;
            o.x = __logf(prev + 1e-30f);
            o.y = __logf(v.x + 1e-30f);
            o.z = __logf(v.y + 1e-30f);
            o.w = __logf(v.z + 1e-30f);
            *reinterpret_cast<float4*>(out + 4 * (size_t)m) = o;
        }
        return;
    }

    // ---------------- recursion role ----------------
    const int b   = blockIdx.x;
    const int tid = threadIdx.x;
    if (tid >= 128) return;           // 4 warps do the work

    const int tgt_t = __ldg(mel_lengths + b)  - 1;   // final time index
    const int tgt_l = __ldg(text_lengths + b) - 1;   // final label index

    const int warp = tid >> 5;
    const int lane = tid & 31;

    // Labels 2*tid and 2*tid+1
    const float* base0 = probs + (size_t)b * LL * TT + (size_t)(2 * tid) * TT;
    const float* base1 = base0 + TT;

    // Double-buffered cross-warp boundary values (lane31.a1 of warps 0..2)
    __shared__ float bnd[2][4];
    if (tid < 4) { bnd[0][tid] = NEGV; bnd[1][tid] = NEGV; }

    float a0 = NEGV, a1 = NEGV;
    if (tid == 0) a0 = __logf(__ldg(base0) + 1e-30f);   // alpha[0][0] = lp[0][0]

    // PF-deep prefetch ring of raw probs for t = 1..
    float pb0[PF], pb1[PF];
#pragma unroll
    for (int d = 0; d < PF; ++d) {
        int tq = 1 + d; if (tq > tgt_t) tq = tgt_t;
        pb0[d] = __ldg(base0 + tq);
        pb1[d] = __ldg(base1 + tq);
    }
    __syncthreads();

#pragma unroll 16
    for (int t = 1; t <= tgt_t; ++t) {
        const int r = (t - 1) & (PF - 1);
        float lp0 = __logf(pb0[r] + 1e-30f);
        float lp1 = __logf(pb1[r] + 1e-30f);
        int tq = t + PF; if (tq > tgt_t) tq = tgt_t;
        pb0[r] = __ldg(base0 + tq);
        pb1[r] = __ldg(base1 + tq);

        // left neighbor of label 2*tid = label 2*tid-1 (prev thread's a1).
        float sh = __shfl_up_sync(0xffffffffu, a1, 1);
        float left0 = (lane == 0) ? ((warp == 0) ? NEGV : bnd[t & 1][warp - 1])
                                  : sh;

        float n0 = lae_add(a0, left0, lp0);
        float n1 = lae_add(a1, a0,    lp1);
        a0 = n0; a1 = n1;

        if (lane == 31 && warp < 3) bnd[(t + 1) & 1][warp] = a1;
        __syncthreads();
    }

    if (tid == (tgt_l >> 1))
        g_alpha_last[b] = (tgt_l & 1) ? a1 : a0;
}

// ---------------------------------------------------------------------------
// Reduce 64 partials -> loss = -mean
// ---------------------------------------------------------------------------
__global__ void k_reduce(float* __restrict__ loss_out)
{
    int i = threadIdx.x; // 32 threads
    float v = g_alpha_last[i] + g_alpha_last[i + 32];
#pragma unroll
    for (int off = 16; off > 0; off >>= 1)
        v += __shfl_down_sync(0xffffffffu, v, off);
    if (i == 0) loss_out[0] = -v * (1.0f / BB);
}

// ---------------------------------------------------------------------------
extern "C" void kernel_launch(void* const* d_in, const int* in_sizes, int n_in,
                              void* d_out, int out_size)
{
    const float* probs        = (const float*)d_in[0];
    // d_in[1] = melspec (unused by the computation)
    const int*   text_lengths = (const int*)d_in[2];
    const int*   mel_lengths  = (const int*)d_in[3];

    float* out = (float*)d_out;   // out[0] = loss, out[1..E_TOTAL] = log matrix

    k_fused<<<BB + NE_BLOCKS, 256>>>(probs, text_lengths, mel_lengths, out);
    k_reduce<<<1, 32>>>(out);
    (void)in_sizes; (void)n_in; (void)out_size;
}

// round 4
// speedup vs baseline: 2.4791x; 1.4638x over previous
#include <cuda_runtime.h>
#include <cuda_bf16.h>
#include <cstdint>

// Problem shape (fixed by dataset)
#define BB 64
#define LL 256
#define TT 1600
#define NEGV (-1e30f)
#define E_TOTAL (BB * LL * TT)          // 26,214,400
#define NE_BLOCKS 25600                 // elementwise blocks: 25600*256 = E_TOTAL/4
#define TC 16                           // time-chunk staged in smem
#define SROW 17                         // smem row stride (floats): 2-way conflicts only

// Scratch for per-batch alpha_last (allocation-free rule: __device__ global)
__device__ float g_alpha_last[BB];

// logaddexp(x,y) + lp, with (m+lp) off the exp/log chain.
__device__ __forceinline__ float lae_add(float x, float y, float lp)
{
    float m = fmaxf(x, y);
    float d = fminf(x, y) - m;          // <= 0, finite; EX2 underflows to 0 safely
    float s = m + lp;                   // runs parallel to exp/log chain
    return s + __logf(1.0f + __expf(d));
}

// ---------------------------------------------------------------------------
// Fused kernel.
//   blocks [0, BB)            : forward recursion, one batch per block,
//                               128 active threads (4 warps), 2 labels/thread.
//                               lp values staged through a double-buffered smem
//                               tile [256 labels x 16 t] filled by coalesced
//                               cp.async — no strided gathers in the hot loop.
//   blocks [BB, BB+NE_BLOCKS) : elementwise log(probs+1e-30) -> out matrix.
// ---------------------------------------------------------------------------
__global__ void __launch_bounds__(256)
k_fused(const float* __restrict__ probs,
        const int* __restrict__ text_lengths,
        const int* __restrict__ mel_lengths,
        float* __restrict__ out)
{
    __shared__ float sbuf[2][LL * SROW];   // 2 x 256 x 17 floats = 34,816 B
    __shared__ float bnd[2][4];            // cross-warp boundary, double-buffered

    if (blockIdx.x >= BB) {
        // ---------------- elementwise role ----------------
        // out[i] = log(probs[i-1] + 1e-30) for i in [1, E_TOTAL].
        unsigned m = (blockIdx.x - BB) * 256u + threadIdx.x;
        if (m == 0) {
            out[1] = __logf(__ldg(probs + 0) + 1e-30f);
            out[2] = __logf(__ldg(probs + 1) + 1e-30f);
            out[3] = __logf(__ldg(probs + 2) + 1e-30f);
            out[(size_t)E_TOTAL] = __logf(__ldg(probs + E_TOTAL - 1) + 1e-30f);
        } else {
            float4 v = __ldg(reinterpret_cast<const float4*>(probs) + m);
            float prev = __ldg(probs + 4 * (size_t)m - 1);   // L1 hit (neighbor's .w)
            float4 o;
            o.x = __logf(prev + 1e-30f);
            o.y = __logf(v.x + 1e-30f);
            o.z = __logf(v.y + 1e-30f);
            o.w = __logf(v.z + 1e-30f);
            *reinterpret_cast<float4*>(out + 4 * (size_t)m) = o;
        }
        return;
    }

    // ---------------- recursion role ----------------
    const int b   = blockIdx.x;
    const int tid = threadIdx.x;
    if (tid >= 128) return;               // 4 warps do the work

    const int tgt_t = __ldg(mel_lengths + b)  - 1;   // final time index
    const int tgt_l = __ldg(text_lengths + b) - 1;   // final label index
    const int warp  = tid >> 5;
    const int lane  = tid & 31;

    const float* pbase = probs + (size_t)b * LL * TT;

    if (tid < 4) { bnd[0][tid] = NEGV; bnd[1][tid] = NEGV; }

    const uint32_t sb_u32 = (uint32_t)__cvta_generic_to_shared(&sbuf[0][0]);

    // Stage chunk 0 (t = 0..15). 256 rows x 16 cols, 4B cp.async.
    // op o: row = o>>4, col = o&15. For fixed (j,h), a warp's 32 lanes cover
    // 2 rows x 64B contiguous -> <=4 lines/instruction (coalesced).
#pragma unroll
    for (int j = 0; j < TC; ++j) {
#pragma unroll
        for (int h = 0; h < 2; ++h) {
            int o   = j * 256 + h * 128 + tid;
            int row = o >> 4, col = o & 15;
            uint32_t sa = sb_u32 + (uint32_t)(row * SROW + col) * 4u;
            const float* g = pbase + (size_t)row * TT + col;
            asm volatile("cp.async.ca.shared.global [%0], [%1], 4;"
                         :: "r"(sa), "l"(g));
        }
    }
    asm volatile("cp.async.commit_group;");
    asm volatile("cp.async.wait_group 0;");
    __syncthreads();

    float a0 = NEGV, a1 = NEGV;
    if (tid == 0) a0 = __logf(sbuf[0][0] + 1e-30f);   // alpha[0][0]

    const int nchunks = tgt_t / TC + 1;

    for (int c = 0; c < nchunks; ++c) {
        const int  cb = c & 1, nb = cb ^ 1;
        const int  g1 = TC * (c + 1);                  // next chunk's first t
        const bool do_stage = (g1 <= tgt_t);           // block-uniform
        const uint32_t snb = sb_u32 + (uint32_t)(nb * LL * SROW) * 4u;
        const float*   gn  = pbase + g1;

#pragma unroll
        for (int j = 0; j < TC; ++j) {
            // Spread next-chunk staging across steps: 2 cp.async per thread-step.
            if (do_stage) {
#pragma unroll
                for (int h = 0; h < 2; ++h) {
                    int o   = j * 256 + h * 128 + tid;
                    int row = o >> 4, col = o & 15;
                    uint32_t sa = snb + (uint32_t)(row * SROW + col) * 4u;
                    const float* g = gn + (size_t)row * TT + col;
                    asm volatile("cp.async.ca.shared.global [%0], [%1], 4;"
                                 :: "r"(sa), "l"(g));
                }
            }
            const int t = TC * c + j;
            if (t >= 1 && t <= tgt_t) {                // block-uniform
                float lp0 = __logf(sbuf[cb][(2 * tid)     * SROW + j] + 1e-30f);
                float lp1 = __logf(sbuf[cb][(2 * tid + 1) * SROW + j] + 1e-30f);

                // left neighbor of label 2*tid = previous thread's a1 (old).
                float sh = __shfl_up_sync(0xffffffffu, a1, 1);
                float left0 = (lane == 0)
                              ? ((warp == 0) ? NEGV : bnd[t & 1][warp - 1])
                              : sh;

                float n0 = lae_add(a0, left0, lp0);
                float n1 = lae_add(a1, a0,    lp1);
                a0 = n0; a1 = n1;

                if (lane == 31 && warp < 3) bnd[(t + 1) & 1][warp] = a1;
                __syncthreads();
            }
        }
        asm volatile("cp.async.commit_group;");
        asm volatile("cp.async.wait_group 0;");
        __syncthreads();
    }

    if (tid == (tgt_l >> 1))
        g_alpha_last[b] = (tgt_l & 1) ? a1 : a0;
}

// ---------------------------------------------------------------------------
// Reduce 64 partials -> loss = -mean
// ---------------------------------------------------------------------------
__global__ void k_reduce(float* __restrict__ loss_out)
{
    int i = threadIdx.x; // 32 threads
    float v = g_alpha_last[i] + g_alpha_last[i + 32];
#pragma unroll
    for (int off = 16; off > 0; off >>= 1)
        v += __shfl_down_sync(0xffffffffu, v, off);
    if (i == 0) loss_out[0] = -v * (1.0f / BB);
}

// ---------------------------------------------------------------------------
extern "C" void kernel_launch(void* const* d_in, const int* in_sizes, int n_in,
                              void* d_out, int out_size)
{
    const float* probs        = (const float*)d_in[0];
    // d_in[1] = melspec (unused by the computation)
    const int*   text_lengths = (const int*)d_in[2];
    const int*   mel_lengths  = (const int*)d_in[3];

    float* out = (float*)d_out;   // out[0] = loss, out[1..E_TOTAL] = log matrix

    k_fused<<<BB + NE_BLOCKS, 256>>>(probs, text_lengths, mel_lengths, out);
    k_reduce<<<1, 32>>>(out);
    (void)in_sizes; (void)n_in; (void)out_size;
}